// round 8
// baseline (speedup 1.0000x reference)
#include <cuda_runtime.h>
#include <cstdint>

#define DIM   512
#define BATCH 32
#define TT    2048
#define G4    2048              // 4*DIM
#define NBLK  128               // persistent blocks for recurrence
#define RTHR  512
#define GRPS  2                 // independent batch groups
#define GRPB  64                // blocks per group
#define GBAT  16                // batches per group
#define HGRP  8192              // floats of h per group (512 dims x 16 b)

// ---------------- device scratch (no allocations allowed) ----------------
__device__ __align__(16) float g_xg[(size_t)TT * G4 * BATCH];   // [t][n][b]
__device__ __align__(16) float g_hbuf[4][GRPS * HGRP];          // 4-deep ring
__device__ unsigned g_flag[NBLK * 8];   // one flag per block, 32B apart

typedef unsigned long long ull;

// ---------------- f32x2 helpers ----------------
__device__ __forceinline__ ull f2fma(ull a, ull b, ull c){
    ull d; asm("fma.rn.f32x2 %0, %1, %2, %3;" : "=l"(d) : "l"(a), "l"(b), "l"(c)); return d;
}
__device__ __forceinline__ ull pk2(float lo, float hi){
    ull r; asm("mov.b64 %0, {%1, %2};" : "=l"(r) : "f"(lo), "f"(hi)); return r;
}
__device__ __forceinline__ float2 upk(ull v){
    float2 f; asm("mov.b64 {%0, %1}, %2;" : "=f"(f.x), "=f"(f.y) : "l"(v)); return f;
}
__device__ __forceinline__ float hadd(ull v){ float2 f = upk(v); return f.x + f.y; }

__device__ __forceinline__ float sigf(float x){ return 1.0f / (1.0f + __expf(-x)); }
__device__ __forceinline__ float tanhfast(float x){
    float e = __expf(2.0f * x);              // inf-safe at both ends
    return 1.0f - 2.0f / (e + 1.0f);
}

// ---------------- scoped sync primitives ----------------
__device__ __forceinline__ void st_release(unsigned* p, unsigned v){
    asm volatile("st.release.gpu.global.u32 [%0], %1;" :: "l"(p), "r"(v) : "memory");
}
__device__ __forceinline__ unsigned ld_acquire(unsigned* p){
    unsigned v;
    asm volatile("ld.acquire.gpu.global.u32 %0, [%1];" : "=r"(v) : "l"(p) : "memory");
    return v;
}
__device__ __forceinline__ void cpa16(unsigned dst, const void* src){
    asm volatile("cp.async.cg.shared.global [%0], [%1], 16;" :: "r"(dst), "l"(src));
}

// =====================================================================
// Kernel 1: xg[t][n][b] = sum_k x[b][t][k]*W_ih[n][k] + b_ih[n] + b_hh[n]
// M = 65536 (m = t*32 + b), N = 2048, K = 512. 128x128x8 tile, f32x2.
// Block (0,0) also re-initializes recurrence state each launch.
// =====================================================================
__global__ void __launch_bounds__(256) gemm_xg_kernel(
    const float* __restrict__ x, const float* __restrict__ Wih,
    const float* __restrict__ bih, const float* __restrict__ bhh)
{
    __shared__ float As[8][128];
    __shared__ float Bs[8][128];
    const int tid = threadIdx.x;

    if (blockIdx.x == 0 && blockIdx.y == 0){     // init (runs before rec kernel)
        for (int i = tid; i < GRPS * HGRP; i += 256) g_hbuf[0][i] = 0.0f;
        for (int i = tid; i < NBLK; i += 256) g_flag[i * 8] = 0u;
    }

    const int bn0 = blockIdx.x * 128;
    const int bm0 = blockIdx.y * 128;
    const int tm0 = (tid >> 4) * 8;
    const int c4  = (tid & 15) * 4;

    const int lr = tid >> 1;
    const int lk = (tid & 1) * 4;
    const int m  = bm0 + lr;
    const float* ap = x + (size_t)(m & 31) * ((size_t)TT * DIM) + (size_t)(m >> 5) * DIM + lk;
    const float* bp = Wih + (size_t)(bn0 + lr) * DIM + lk;

    ull c2[4][8];
    #pragma unroll
    for (int i = 0; i < 4; i++)
        #pragma unroll
        for (int j = 0; j < 8; j++) c2[i][j] = 0ULL;

    float4 av = *(const float4*)ap;
    float4 bv = *(const float4*)bp;

    for (int k0 = 0; k0 < DIM; k0 += 8){
        As[lk+0][lr]=av.x; As[lk+1][lr]=av.y; As[lk+2][lr]=av.z; As[lk+3][lr]=av.w;
        Bs[lk+0][lr]=bv.x; Bs[lk+1][lr]=bv.y; Bs[lk+2][lr]=bv.z; Bs[lk+3][lr]=bv.w;
        __syncthreads();
        if (k0 + 8 < DIM){
            av = *(const float4*)(ap + k0 + 8);
            bv = *(const float4*)(bp + k0 + 8);
        }
        #pragma unroll
        for (int kk = 0; kk < 8; kk++){
            const ulonglong2* arow = (const ulonglong2*)&As[kk][tm0];
            ulonglong2 a01 = arow[0];
            ulonglong2 a23 = arow[1];
            float4 bl = *(const float4*)&Bs[kk][c4];
            float4 bh = *(const float4*)&Bs[kk][c4 + 64];
            ull bd[8];
            bd[0]=pk2(bl.x,bl.x); bd[1]=pk2(bl.y,bl.y); bd[2]=pk2(bl.z,bl.z); bd[3]=pk2(bl.w,bl.w);
            bd[4]=pk2(bh.x,bh.x); bd[5]=pk2(bh.y,bh.y); bd[6]=pk2(bh.z,bh.z); bd[7]=pk2(bh.w,bh.w);
            #pragma unroll
            for (int j = 0; j < 8; j++){
                c2[0][j] = f2fma(a01.x, bd[j], c2[0][j]);
                c2[1][j] = f2fma(a01.y, bd[j], c2[1][j]);
                c2[2][j] = f2fma(a23.x, bd[j], c2[2][j]);
                c2[3][j] = f2fma(a23.y, bd[j], c2[3][j]);
            }
        }
        __syncthreads();
    }

    float bias[8];
    #pragma unroll
    for (int j = 0; j < 8; j++){
        int n = bn0 + c4 + (j & 3) + ((j >> 2) << 6);
        bias[j] = bih[n] + bhh[n];
    }
    #pragma unroll
    for (int i = 0; i < 8; i++){
        int mg = bm0 + tm0 + i;
        size_t obase = (size_t)(mg >> 5) * ((size_t)G4 * BATCH) + (size_t)(mg & 31);
        #pragma unroll
        for (int j = 0; j < 8; j++){
            float2 p = upk(c2[i >> 1][j]);
            float v = (i & 1) ? p.y : p.x;
            int n = bn0 + c4 + (j & 3) + ((j >> 2) << 6);
            g_xg[obase + (size_t)n * BATCH] = v + bias[j];
        }
    }
}

// =====================================================================
// Kernel 2: persistent recurrence, batch-split into 2 independent
// groups of 64 blocks (group grp = bx>>6 owns batches [grp*16,+16);
// block gb = bx&63 owns dims [gb*8, gb*8+8), all 4 gates).
// 512 threads = 16 warps; warp kh owns k-slice [kh*32,+32); lane =
// (bq = l&3 -> batches bq+4j, dl = l>>2 -> dim). Thread: 4 gates x
// 4 batches x 1 dim over 32 k. Warp kh's h slice is produced by group
// blocks kh*4..kh*4+3 -> poll 4 flags, cp.async own 2KB slice, FMA.
// Reduce: warp = (gate, batch-quad); lane = (batch, dim). Owners
// (tid<128: b=tid>>3, d=tid&7) update c, store h, named-bar, release.
// h ring is 4-deep (WAR-safe by poll transitivity within the group).
// =====================================================================
__global__ void __launch_bounds__(RTHR) lstm_rec_kernel(
    const float* __restrict__ Whh, float* __restrict__ out)
{
    extern __shared__ float sm[];
    float* shW = sm;                       // 32 rows x 516 floats (padded)
    float* shH = shW + 32 * 516;           // [128 k4][16 b][4] = 8192 floats
    float* shR = shH + HGRP;               // [16 kh][520] partials
    float* shG = shR + 16 * 520;           // [4 g][16 b][8 d] = 512 floats

    const int tid  = threadIdx.x;
    const int bx   = blockIdx.x;
    const int grp  = bx >> 6;
    const int gb   = bx & 63;
    const int kh   = tid >> 5;             // warp id = k-slice
    const int lane = tid & 31;
    const int bq   = lane & 3;
    const int dl   = lane >> 2;

    // Load this block's 32 W_hh rows into padded shared (once).
    for (int idx = tid; idx < 32 * 128; idx += RTHR){
        int rl = idx >> 7;                 // g*8 + dloc
        int k4 = idx & 127;
        int g = rl >> 3, dloc = rl & 7;
        *(float4*)(shW + rl * 516 + k4 * 4) =
            *(const float4*)(Whh + (size_t)(g * DIM + gb * 8 + dloc) * DIM + k4 * 4);
    }

    const ulonglong2* w0 = (const ulonglong2*)(shW + (0*8 + dl) * 516 + kh * 32);
    const ulonglong2* w1 = (const ulonglong2*)(shW + (1*8 + dl) * 516 + kh * 32);
    const ulonglong2* w2 = (const ulonglong2*)(shW + (2*8 + dl) * 516 + kh * 32);
    const ulonglong2* w3 = (const ulonglong2*)(shW + (3*8 + dl) * 516 + kh * 32);
    const ulonglong2* hp = ((const ulonglong2*)shH) + kh * 128 + bq;

    // staging: warp kh stages its 2KB slice (128 float4), 4 per lane
    const unsigned stg =
        (unsigned)__cvta_generic_to_shared(shH) + (unsigned)(kh * 128 + lane) * 16u;
    const int stg_src = grp * (HGRP / 4) + kh * 128 + lane;   // float4 index

    // poll: producers of k-slice kh are group blocks kh*4 .. kh*4+3
    unsigned* pf = &g_flag[(grp * GRPB + kh * 4 + (lane & 3)) * 8];

    // reduce role: warp kh = (rg = kh>>2 gate, rq = kh&3 batch-quad)
    const int rg = kh >> 2, rq = kh & 3;
    const int r_out = (rg * 16 + rq * 4 + (lane >> 3)) * 8 + (lane & 7);
    const size_t xoffs = (size_t)(rg * DIM + gb * 8 + (lane & 7)) * BATCH
                       + (size_t)(grp * GBAT + rq * 4 + (lane >> 3));

    // owner role (tid < 128): b = tid>>3 (local), d = tid&7
    const int ob = tid >> 3, od = tid & 7;
    const int D  = gb * 8 + od;
    const int Bg = grp * GBAT + ob;
    const int hwidx = grp * HGRP + (D >> 2) * (GBAT * 4) + ob * 4 + (D & 3);
    float* outp = out + (size_t)Bg * ((size_t)TT * DIM) + D;
    unsigned* myflag = &g_flag[(grp * GRPB + gb) * 8];

    float cc = 0.0f;
    __syncthreads();                       // W ready

    for (int t = 0; t < TT; t++){
        // xg prefetch (independent of h)
        float xv = __ldcg(g_xg + (size_t)t * ((size_t)G4 * BATCH) + xoffs);

        // ---- per-warp poll: my 4 producers reached step t ----
        if (lane < 4){
            while (ld_acquire(pf) < (unsigned)t) { }
        }
        __syncwarp();

        // ---- stage my 2KB h slice via cp.async ----
        const float4* hsrc = (const float4*)g_hbuf[t & 3] + stg_src;
        #pragma unroll
        for (int q = 0; q < 4; q++)
            cpa16(stg + q * 512u, hsrc + q * 32);
        asm volatile("cp.async.commit_group;");
        asm volatile("cp.async.wait_group 0;");
        __syncwarp();

        // ---- partial gates: 4 gates x 4 batches x 1 dim over 32 k ----
        ull acc[4][4];
        #pragma unroll
        for (int g = 0; g < 4; g++)
            #pragma unroll
            for (int j = 0; j < 4; j++) acc[g][j] = 0ULL;

        #pragma unroll
        for (int i = 0; i < 8; i++){
            ulonglong2 h0 = hp[i * 16];
            ulonglong2 h1 = hp[i * 16 + 4];
            ulonglong2 h2 = hp[i * 16 + 8];
            ulonglong2 h3 = hp[i * 16 + 12];
            ulonglong2 v0 = w0[i], v1 = w1[i], v2 = w2[i], v3 = w3[i];
            acc[0][0]=f2fma(h0.x,v0.x,acc[0][0]); acc[0][0]=f2fma(h0.y,v0.y,acc[0][0]);
            acc[0][1]=f2fma(h1.x,v0.x,acc[0][1]); acc[0][1]=f2fma(h1.y,v0.y,acc[0][1]);
            acc[0][2]=f2fma(h2.x,v0.x,acc[0][2]); acc[0][2]=f2fma(h2.y,v0.y,acc[0][2]);
            acc[0][3]=f2fma(h3.x,v0.x,acc[0][3]); acc[0][3]=f2fma(h3.y,v0.y,acc[0][3]);
            acc[1][0]=f2fma(h0.x,v1.x,acc[1][0]); acc[1][0]=f2fma(h0.y,v1.y,acc[1][0]);
            acc[1][1]=f2fma(h1.x,v1.x,acc[1][1]); acc[1][1]=f2fma(h1.y,v1.y,acc[1][1]);
            acc[1][2]=f2fma(h2.x,v1.x,acc[1][2]); acc[1][2]=f2fma(h2.y,v1.y,acc[1][2]);
            acc[1][3]=f2fma(h3.x,v1.x,acc[1][3]); acc[1][3]=f2fma(h3.y,v1.y,acc[1][3]);
            acc[2][0]=f2fma(h0.x,v2.x,acc[2][0]); acc[2][0]=f2fma(h0.y,v2.y,acc[2][0]);
            acc[2][1]=f2fma(h1.x,v2.x,acc[2][1]); acc[2][1]=f2fma(h1.y,v2.y,acc[2][1]);
            acc[2][2]=f2fma(h2.x,v2.x,acc[2][2]); acc[2][2]=f2fma(h2.y,v2.y,acc[2][2]);
            acc[2][3]=f2fma(h3.x,v2.x,acc[2][3]); acc[2][3]=f2fma(h3.y,v2.y,acc[2][3]);
            acc[3][0]=f2fma(h0.x,v3.x,acc[3][0]); acc[3][0]=f2fma(h0.y,v3.y,acc[3][0]);
            acc[3][1]=f2fma(h1.x,v3.x,acc[3][1]); acc[3][1]=f2fma(h1.y,v3.y,acc[3][1]);
            acc[3][2]=f2fma(h2.x,v3.x,acc[3][2]); acc[3][2]=f2fma(h2.y,v3.y,acc[3][2]);
            acc[3][3]=f2fma(h3.x,v3.x,acc[3][3]); acc[3][3]=f2fma(h3.y,v3.y,acc[3][3]);
        }

        // ---- partials: shR[kh][(g*16 + bq+4j)*8 + dl]  (conflict-free) ----
        #pragma unroll
        for (int g = 0; g < 4; g++)
            #pragma unroll
            for (int j = 0; j < 4; j++)
                shR[kh * 520 + (g * 16 + bq + 4*j) * 8 + dl] = hadd(acc[g][j]);
        __syncthreads();                   // bar1: all partials in

        // ---- reduce over 16 kh + nonlinearity (all 512 threads) ----
        {
            float s = xv;
            #pragma unroll
            for (int k = 0; k < 16; k++) s += shR[k * 520 + r_out];
            shG[r_out] = (rg == 2) ? tanhfast(s) : sigf(s);
        }
        __syncthreads();                   // bar2: gates ready

        // ---- owners: c/h update, store h, release; others loop on ----
        if (tid < 128){
            float iv = shG[tid];
            float fv = shG[128 + tid];
            float gv = shG[256 + tid];
            float ov = shG[384 + tid];
            cc = fv * cc + iv * gv;
            float hv = ov * tanhfast(cc);
            g_hbuf[(t + 1) & 3][hwidx] = hv;
            asm volatile("bar.sync 1, 128;");          // owners only
            if (tid == 0 && t + 1 < TT)
                st_release(myflag, (unsigned)(t + 1));
            outp[(size_t)t * DIM] = hv;                // overlaps next poll
        }
    }
}

// =====================================================================
extern "C" void kernel_launch(void* const* d_in, const int* in_sizes, int n_in,
                              void* d_out, int out_size)
{
    (void)in_sizes; (void)n_in; (void)out_size;
    const float* x    = (const float*)d_in[0];
    const float* Wih  = (const float*)d_in[1];
    const float* Whh  = (const float*)d_in[2];
    const float* bih  = (const float*)d_in[3];
    const float* bhh  = (const float*)d_in[4];
    float* out = (float*)d_out;

    // shW 32*516 + shH 8192 + shR 16*520 + shG 512 = 33536 floats = 134144 B
    cudaFuncSetAttribute(lstm_rec_kernel,
                         cudaFuncAttributeMaxDynamicSharedMemorySize, 134144);

    dim3 ggrid(G4 / 128, (BATCH * TT) / 128);
    gemm_xg_kernel<<<ggrid, 256>>>(x, Wih, bih, bhh);
    lstm_rec_kernel<<<NBLK, RTHR, 134144>>>(Whh, out);
}